// round 1
// baseline (speedup 1.0000x reference)
#include <cuda_runtime.h>
#include <cstdint>
#include <math.h>

// Gridding: trilinear scatter of B x N points into B x (64^3) grids.
// scale = 32 (half extent), G = 64.
#define HALF  32
#define GSIDE 64
#define GRID3 (GSIDE * GSIDE * GSIDE)

// Fire-and-forget global reductions (no return value -> RED, not ATOM).
__device__ __forceinline__ void red_f32(float* a, float v) {
    asm volatile("red.global.add.f32 [%0], %1;" :: "l"(a), "f"(v) : "memory");
}
__device__ __forceinline__ void red_v2(float* a, float v0, float v1) {
    asm volatile("red.global.add.v2.f32 [%0], {%1,%2};"
                 :: "l"(a), "f"(v0), "f"(v1) : "memory");
}
__device__ __forceinline__ void red_v4(float* a, float v0, float v1, float v2, float v3) {
    asm volatile("red.global.add.v4.f32 [%0], {%1,%2,%3,%4};"
                 :: "l"(a), "f"(v0), "f"(v1), "f"(v2), "f"(v3) : "memory");
}

__global__ void gridding_scatter_kernel(const float* __restrict__ pt,
                                        float* __restrict__ out,
                                        int N) {
    int n = blockIdx.x * blockDim.x + threadIdx.x;
    int b = blockIdx.y;
    if (n >= N) return;

    const float* p = pt + ((size_t)b * N + n) * 3;
    float x = p[0] * (float)HALF;
    float y = p[1] * (float)HALF;
    float z = p[2] * (float)HALF;

    // reference: points whose (scaled) coord-sum is exactly 0 get weight 0
    float m = ((x + y + z) != 0.0f) ? 1.0f : 0.0f;

    float fx = floorf(x), fy = floorf(y), fz = floorf(z);
    float tx = x - fx, ty = y - fy, tz = z - fz;

    int ix = min(max((int)fx + HALF, 0), GSIDE - 2);
    int iy = min(max((int)fy + HALF, 0), GSIDE - 2);
    int iz = min(max((int)fz + HALF, 0), GSIDE - 2);

    float wx0 = 1.0f - tx, wx1 = tx;
    float wy0 = 1.0f - ty, wy1 = ty;
    float wz0 = (1.0f - tz) * m;
    float wz1 = tz * m;

    float w00 = wx0 * wy0;   // (x, y)
    float w01 = wx0 * wy1;   // (x, y+1)
    float w10 = wx1 * wy0;   // (x+1, y)
    float w11 = wx1 * wy1;   // (x+1, y+1)

    float* g   = out + (size_t)b * GRID3;
    float* r00 = g + (((size_t)ix * GSIDE + iy) * GSIDE + iz);
    float* r01 = r00 + GSIDE;
    float* r10 = r00 + GSIDE * GSIDE;
    float* r11 = r10 + GSIDE;

    // z-pair (iz, iz+1) is contiguous. Vectorize the reduction when alignment allows:
    //   iz % 2 == 0 : one red.v2 per (x,y) corner  (4 lanes/point)
    //   iz % 4 == 1 : one zero-padded red.v4 at iz-1 (4 lanes/point)
    //   iz % 4 == 3 : two scalar reds (8 lanes/point)
    if ((iz & 1) == 0) {
        red_v2(r00, w00 * wz0, w00 * wz1);
        red_v2(r01, w01 * wz0, w01 * wz1);
        red_v2(r10, w10 * wz0, w10 * wz1);
        red_v2(r11, w11 * wz0, w11 * wz1);
    } else if ((iz & 3) == 1) {
        red_v4(r00 - 1, 0.0f, w00 * wz0, w00 * wz1, 0.0f);
        red_v4(r01 - 1, 0.0f, w01 * wz0, w01 * wz1, 0.0f);
        red_v4(r10 - 1, 0.0f, w10 * wz0, w10 * wz1, 0.0f);
        red_v4(r11 - 1, 0.0f, w11 * wz0, w11 * wz1, 0.0f);
    } else {  // iz % 4 == 3
        red_f32(r00, w00 * wz0); red_f32(r00 + 1, w00 * wz1);
        red_f32(r01, w01 * wz0); red_f32(r01 + 1, w01 * wz1);
        red_f32(r10, w10 * wz0); red_f32(r10 + 1, w10 * wz1);
        red_f32(r11, w11 * wz0); red_f32(r11 + 1, w11 * wz1);
    }
}

extern "C" void kernel_launch(void* const* d_in, const int* in_sizes, int n_in,
                              void* d_out, int out_size) {
    const float* pt  = (const float*)d_in[0];
    float*       out = (float*)d_out;

    // out_size = B * 64^3 ; in_sizes[0] = B * N * 3
    int B = out_size / GRID3;
    if (B < 1) B = 1;
    int N = (in_sizes[0] / 3) / B;

    // d_out is poisoned; atomics need zero-init.
    cudaMemsetAsync(d_out, 0, (size_t)out_size * sizeof(float));

    dim3 block(256, 1, 1);
    dim3 grid((N + block.x - 1) / block.x, B, 1);
    gridding_scatter_kernel<<<grid, block>>>(pt, out, N);
}